// round 7
// baseline (speedup 1.0000x reference)
#include <cuda_runtime.h>
#include <cuda_fp16.h>
#include <math.h>

#define DIM (1u << 18)
#define CELLS (1u << 17)
#define BATCH 64

typedef unsigned long long pk;  // packed f32x2 (lane0 = low word = even amp)

// Interleaved fp16 state: cell = {half2 X (re pair), half2 Y (im pair)}.
// Ping-pong buffers, 2 x 64 MB static scratch.
__device__ uint2 g_s0[BATCH * CELLS];
__device__ uint2 g_s1[BATCH * CELLS];
// Readout diagonal dd[x] (CNOT perm + (c^2)^108 + 1/256 folded in).
__device__ __align__(8) float g_dd[DIM];

#define TAU 0.05004170837554f  // tan(0.05); gate A/c^2 = I + tau*(..) + tau^2*(..)

__device__ __forceinline__ pk pack2(float lo, float hi) {
    pk r; asm("mov.b64 %0,{%1,%2};" : "=l"(r) : "f"(lo), "f"(hi)); return r;
}
__device__ __forceinline__ void unpack2(pk p, float& lo, float& hi) {
    asm("mov.b64 {%0,%1},%2;" : "=f"(lo), "=f"(hi) : "l"(p));
}
__device__ __forceinline__ pk fma2(pk a, pk b, pk c) {
    pk d; asm("fma.rn.f32x2 %0,%1,%2,%3;" : "=l"(d) : "l"(a), "l"(b), "l"(c)); return d;
}
__device__ __forceinline__ pk mul2(pk a, pk b) {
    pk d; asm("mul.rn.f32x2 %0,%1,%2;" : "=l"(d) : "l"(a), "l"(b)); return d;
}
__device__ __forceinline__ pk swap2(pk p) { float lo, hi; unpack2(p, lo, hi); return pack2(hi, lo); }

__device__ __forceinline__ pk h2f(unsigned h) {
    float2 f = __half22float2(*(const __half2*)&h);
    return pack2(f.x, f.y);
}
__device__ __forceinline__ unsigned f2h(pk p) {
    float a0, a1; unpack2(p, a0, a1);
    __half2 h = __floats2half2_rn(a0, a1);
    return *(unsigned*)&h;
}

struct KC { pk Tp, Tn, T2p, T2n; };
__device__ __forceinline__ KC mkKC() {
    const float t = TAU, t2 = TAU * TAU;
    KC k; k.Tp = pack2(t, t); k.Tn = pack2(-t, -t);
    k.T2p = pack2(t2, t2); k.T2n = pack2(-t2, -t2); return k;
}

// Two independent scaled butterflies (one per SIMD lane), 12 fma2.
__device__ __forceinline__ void bfly2t(pk& Xa, pk& Ya, pk& Xb, pk& Yb, const KC& k) {
    pk nXa = fma2(Yb, k.Tp, fma2(Xb, k.Tn, fma2(Ya, k.T2n, Xa)));
    pk nYa = fma2(Yb, k.Tn, fma2(Xb, k.Tn, fma2(Xa, k.T2p, Ya)));
    pk nXb = fma2(Xa, k.Tp, fma2(Ya, k.Tp, fma2(Yb, k.T2p, Xb)));
    pk nYb = fma2(Xa, k.Tn, fma2(Ya, k.Tp, fma2(Xb, k.T2n, Yb)));
    Xa = nXa; Ya = nYa; Xb = nXb; Yb = nYb;
}

// Gate on 4 register-index bits of a 16-pack array.
__device__ __forceinline__ void clean4(pk X[16], pk Y[16], const KC& k) {
#pragma unroll
    for (int bit = 0; bit < 4; bit++)
#pragma unroll
        for (int m = 0; m < 16; m++)
            if (!(m & (1 << bit))) {
                const int n = m | (1 << bit);
                bfly2t(X[m], Y[m], X[n], Y[n], k);
            }
}

// Gate on global bit 0 (the SIMD lane inside the pack).
__device__ __forceinline__ void bflyL(pk& X, pk& Y, const KC& k) {
    const float t = TAU, t2 = TAU * TAU;
    const pk Tm = pack2(-t, t), T2m = pack2(-t2, t2), T2m2 = pack2(t2, -t2);
    pk sX = swap2(X), sY = swap2(Y);
    pk nX = fma2(sY, k.Tp, fma2(sX, Tm, fma2(Y, T2m, X)));
    pk nY = fma2(sY, Tm, fma2(sX, k.Tn, fma2(X, T2m2, Y)));
    X = nX; Y = nY;
}

// CNOT-ring label permutation (wire w <-> bit 17-w). Linear over XOR.
__device__ __forceinline__ unsigned cmap(unsigned x) {
    unsigned sx = x;
    sx ^= sx >> 1; sx ^= sx >> 2; sx ^= sx >> 4; sx ^= sx >> 8; sx ^= sx >> 16;
    return (sx & 0x1FFFFu) | (((sx ^ (x >> 17)) & 1u) << 17);
}

#define PADC(c) ((c) + ((c) >> 4))

// ---------------------------------------------------------------------------
// LO pass: gates on x bits 0..12. Slab = 4096 cells. 256 threads x 16 packs.
// Phase order (gates commute): lane bit + cell bits 0..3 (contiguous load) |
// T1 -> cell bits 4..7 | T2 -> cell bits 8..11 (coalesced store). 2 transposes.
// ---------------------------------------------------------------------------
__global__ void __launch_bounds__(256, 2) pass_lo(uint2* __restrict__ s,
                                                  const float* __restrict__ re,
                                                  const float* __restrict__ im,
                                                  int first) {
    extern __shared__ pk sm[];
    pk* sx = sm;          // 4352 pk
    pk* sy = sm + 4352;   // 4352 pk
    const int t = threadIdx.x;
    const unsigned b = blockIdx.x >> 5, hi = blockIdx.x & 31;
    const size_t cb = ((size_t)b << 17) | ((size_t)hi << 12);
    const KC k = mkKC();

    pk X[16], Y[16];
    // layoutC: cell = 16t + r (thread-contiguous, 128B vector loads)
    if (first) {
        const pk s16 = pack2(16.0f, 16.0f);
        const float* pre = re + 2 * (cb + ((size_t)t << 4));
        const float* pim = im + 2 * (cb + ((size_t)t << 4));
#pragma unroll
        for (int r = 0; r < 16; r++) {
            X[r] = mul2(*(const pk*)(pre + 2 * r), s16);
            Y[r] = mul2(*(const pk*)(pim + 2 * r), s16);
        }
    } else {
        const uint4* p4 = (const uint4*)(s + cb + ((size_t)t << 4));
#pragma unroll
        for (int q = 0; q < 8; q++) {
            const uint4 v = p4[q];
            X[2 * q] = h2f(v.x); Y[2 * q] = h2f(v.y);
            X[2 * q + 1] = h2f(v.z); Y[2 * q + 1] = h2f(v.w);
        }
    }

#pragma unroll
    for (int m = 0; m < 16; m++) bflyL(X[m], Y[m], k);   // x bit 0
    clean4(X, Y, k);                                      // x bits 1..4 (cell 0..3)

    const unsigned tlo = t & 15, thi = t >> 4;
    // T1: layoutC -> layoutB (c = thi<<8 | r<<4 | tlo; reg = cell bits 4..7)
#pragma unroll
    for (int r = 0; r < 16; r++) { const unsigned c = ((unsigned)t << 4) | r; sx[PADC(c)] = X[r]; sy[PADC(c)] = Y[r]; }
    __syncthreads();
#pragma unroll
    for (int r = 0; r < 16; r++) {
        const unsigned c = (thi << 8) | ((unsigned)r << 4) | tlo;
        X[r] = sx[PADC(c)]; Y[r] = sy[PADC(c)];
    }
    clean4(X, Y, k);                                      // x bits 5..8
    __syncthreads();

    // T2: layoutB -> layoutA (c = r<<8 | t; reg = cell bits 8..11)
#pragma unroll
    for (int r = 0; r < 16; r++) {
        const unsigned c = (thi << 8) | ((unsigned)r << 4) | tlo;
        sx[PADC(c)] = X[r]; sy[PADC(c)] = Y[r];
    }
    __syncthreads();
#pragma unroll
    for (int r = 0; r < 16; r++) {
        const unsigned c = ((unsigned)r << 8) | (unsigned)t;
        X[r] = sx[PADC(c)]; Y[r] = sy[PADC(c)];
    }
    clean4(X, Y, k);                                      // x bits 9..12

    // store layoutA: coalesced 8B per cell (256B per warp per r)
#pragma unroll
    for (int r = 0; r < 16; r++) {
        const size_t c = cb + (unsigned)((r << 8) | t);
        s[c] = make_uint2(f2h(X[r]), f2h(Y[r]));
    }
}

// ---------------------------------------------------------------------------
// HI gates (x bits 13..17): cell bits 12..15 = reg r, cell bit 16 = lane bit 4.
// ---------------------------------------------------------------------------
__device__ __forceinline__ void hi_load_gates(const uint2* __restrict__ s,
                                              size_t bb, unsigned clo, int L4,
                                              const KC& k, pk X[16], pk Y[16]) {
#pragma unroll
    for (int r = 0; r < 16; r++) {
        const uint2 v = s[bb + (clo | ((unsigned)r << 12))];
        X[r] = h2f(v.x);
        Y[r] = h2f(v.y);
    }
    clean4(X, Y, k);   // x bits 13..16

    // x bit 17 via shfl_xor(16); a-side (L4=0): e=-TAU, b-side: e=+TAU
    const float e = L4 ? TAU : -TAU;
    const pk eT = pack2(e, e), eT2 = pack2(e * TAU, e * TAU), eT2n = pack2(-e * TAU, -e * TAU);
#pragma unroll
    for (int r = 0; r < 16; r++) {
        pk pX = __shfl_xor_sync(0xffffffffu, X[r], 16);
        pk pY = __shfl_xor_sync(0xffffffffu, Y[r], 16);
        pk nX = fma2(pY, k.Tp, fma2(pX, eT, fma2(Y[r], eT2, X[r])));
        pk nY = fma2(pY, eT, fma2(pX, k.Tn, fma2(X[r], eT2n, Y[r])));
        X[r] = nX; Y[r] = nY;
    }
}

// ---------------------------------------------------------------------------
// HI pass + CNOT permutation folded into the store.
// dst cell pair (y, y^1): sources x and x^0x30001. Partner pack at
// (lane^16, reg^8); reassembled with prmt, parity-selected.
// ---------------------------------------------------------------------------
__global__ void __launch_bounds__(256) pass_hi(const uint2* __restrict__ src,
                                               uint2* __restrict__ dst) {
    const int t = threadIdx.x, L = t & 31, W = t >> 5, L4 = (L >> 4) & 1;
    const unsigned b = blockIdx.x >> 5, mid = blockIdx.x & 31;
    const size_t bb = (size_t)b << 17;
    const unsigned clo = (mid << 7) | ((unsigned)W << 4) | (unsigned)(L & 15)
                       | ((unsigned)L4 << 16);
    const KC k = mkKC();

    pk X[16], Y[16];
    hi_load_gates(src, bb, clo, L4, k, X, Y);

    unsigned hx[16], hy[16];
#pragma unroll
    for (int r = 0; r < 16; r++) { hx[r] = f2h(X[r]); hy[r] = f2h(Y[r]); }

    const unsigned cB = cmap(clo << 1);
    const int pb = __popc(clo) & 1;
#pragma unroll
    for (int r = 0; r < 16; r++) {
        const unsigned phx = __shfl_xor_sync(0xffffffffu, hx[r ^ 8], 16);
        const unsigned phy = __shfl_xor_sync(0xffffffffu, hy[r ^ 8], 16);
        const int pr = pb ^ (__popc((unsigned)r) & 1);
        const unsigned ctrl = pr ? 0x5432u : 0x7610u;
        const unsigned ox = __byte_perm(hx[r], phx, ctrl);
        const unsigned oy = __byte_perm(hy[r], phy, ctrl);
        const unsigned y = cB ^ cmap((unsigned)r << 13) ^ (pr ? 0x20001u : 0u);
        dst[bb + (y >> 1)] = make_uint2(ox, oy);
    }
}

// ---------------------------------------------------------------------------
// Final: HI gates of layer 3 + weighted |.|^2 readout (perm + scales in dd).
// ---------------------------------------------------------------------------
__global__ void __launch_bounds__(256) pass_reduce(const uint2* __restrict__ src,
                                                   float* __restrict__ out) {
    const int t = threadIdx.x, L = t & 31, W = t >> 5, L4 = (L >> 4) & 1;
    const unsigned b = blockIdx.x >> 5, mid = blockIdx.x & 31;
    const size_t bb = (size_t)b << 17;
    const unsigned clo = (mid << 7) | ((unsigned)W << 4) | (unsigned)(L & 15)
                       | ((unsigned)L4 << 16);
    const KC k = mkKC();

    pk X[16], Y[16];
    hi_load_gates(src, bb, clo, L4, k, X, Y);

    pk acc = pack2(0.0f, 0.0f);
#pragma unroll
    for (int r = 0; r < 16; r++) {
        const unsigned c = clo | ((unsigned)r << 12);
        const pk dpk = *(const pk*)(g_dd + ((size_t)c << 1));
        pk p2 = fma2(Y[r], Y[r], mul2(X[r], X[r]));
        acc = fma2(p2, dpk, acc);
    }
    float a0, a1; unpack2(acc, a0, a1);
    float a = a0 + a1;
#pragma unroll
    for (int o = 16; o; o >>= 1) a += __shfl_xor_sync(0xffffffffu, a, o);
    __shared__ float ws[8];
    if (L == 0) ws[W] = a;
    __syncthreads();
    if (t < 8) {
        float ssum = ws[t];
#pragma unroll
        for (int o = 4; o; o >>= 1) ssum += __shfl_xor_sync(0xffu, ssum, o);
        if (t == 0) atomicAdd(out + b, ssum);
    }
}

// ---------------------------------------------------------------------------
// Init dd[] and out[b] = head_b (out is poisoned before each timed run).
// ---------------------------------------------------------------------------
__global__ void __launch_bounds__(256) init_kernel(const float* __restrict__ hw,
                                                   const float* __restrict__ hb,
                                                   float* __restrict__ out, float scale) {
    const unsigned x = blockIdx.x * 256u + threadIdx.x;
    if (x < DIM) {
        const unsigned y = cmap(x);
        float d = 0.0f;
#pragma unroll
        for (int w = 0; w < 18; w++)
            d += hw[w] * (((y >> (17 - w)) & 1u) ? -1.0f : 1.0f);
        g_dd[x] = d * scale;
    }
    if (x < BATCH) out[x] = hb[0];
}

extern "C" void kernel_launch(void* const* d_in, const int* in_sizes, int n_in,
                              void* d_out, int out_size) {
    (void)in_sizes; (void)n_in; (void)out_size;
    const float* re = (const float*)d_in[0];
    const float* im = (const float*)d_in[1];
    const float* hw = (const float*)d_in[2];
    const float* hb = (const float*)d_in[3];
    float* out = (float*)d_out;

    uint2 *s0, *s1;
    cudaGetSymbolAddress((void**)&s0, g_s0);
    cudaGetSymbolAddress((void**)&s1, g_s1);

    const int smemLO = 2 * 4352 * (int)sizeof(pk);  // 69632 B
    cudaFuncSetAttribute(pass_lo, cudaFuncAttributeMaxDynamicSharedMemorySize, smemLO);

    // deferred gate scale: (c^2)^108 for probs; /256 for the x16 input scaling
    const float scale = (float)(pow(0.9975020826390129, 108.0) / 256.0);

    const int grid = BATCH * 32;  // 2048 CTAs x 256 thr

    init_kernel<<<DIM / 256, 256>>>(hw, hb, out, scale);

    // Layer 1
    pass_lo<<<grid, 256, smemLO>>>(s0, re, im, 1);
    pass_hi<<<grid, 256>>>(s0, s1);
    // Layer 2
    pass_lo<<<grid, 256, smemLO>>>(s1, re, im, 0);
    pass_hi<<<grid, 256>>>(s1, s0);
    // Layer 3
    pass_lo<<<grid, 256, smemLO>>>(s0, re, im, 0);
    pass_reduce<<<grid, 256>>>(s0, out);
}

// round 10
// speedup vs baseline: 1.3238x; 1.3238x over previous
#include <cuda_runtime.h>
#include <cuda_fp16.h>
#include <math.h>

#define DIM (1u << 18)
#define CELLS (1u << 17)
#define BATCH 64

typedef unsigned long long pk;  // packed f32x2 (lane0 = low word = even amp)

// fp16 SoA planes, ping-pong. 4 x 32 MB static scratch.
__device__ __half2 g_x0[BATCH * CELLS];
__device__ __half2 g_y0[BATCH * CELLS];
__device__ __half2 g_x1[BATCH * CELLS];
__device__ __half2 g_y1[BATCH * CELLS];
// Readout diagonal dd[x] (CNOT perm + (c^2)^108 + 1/256 folded in).
__device__ __align__(8) float g_dd[DIM];

#define TAU 0.05004170837554f  // tan(0.05); RX/c = I - i*tau*X, RY/c = I + tau*(iY)

__device__ __forceinline__ pk pack2(float lo, float hi) {
    pk r; asm("mov.b64 %0,{%1,%2};" : "=l"(r) : "f"(lo), "f"(hi)); return r;
}
__device__ __forceinline__ void unpack2(pk p, float& lo, float& hi) {
    asm("mov.b64 {%0,%1},%2;" : "=f"(lo), "=f"(hi) : "l"(p));
}
__device__ __forceinline__ pk fma2(pk a, pk b, pk c) {
    pk d; asm("fma.rn.f32x2 %0,%1,%2,%3;" : "=l"(d) : "l"(a), "l"(b), "l"(c)); return d;
}
__device__ __forceinline__ pk mul2(pk a, pk b) {
    pk d; asm("mul.rn.f32x2 %0,%1,%2;" : "=l"(d) : "l"(a), "l"(b)); return d;
}

struct KC { pk Tp, Tn; };
__device__ __forceinline__ KC mkKC() {
    KC k; k.Tp = pack2(TAU, TAU); k.Tn = pack2(-TAU, -TAU); return k;
}

// Two independent butterflies (one per SIMD lane), RX then RY, 8 fma2.
// RX/c: nXa = Xa + t*Yb; nYa = Ya - t*Xb; nXb = Xb + t*Ya; nYb = Yb - t*Xa
// RY/c: Xa' = nXa - t*nXb; Ya' = nYa - t*nYb; Xb' = nXb + t*nXa; Yb' = nYb + t*nYa
__device__ __forceinline__ void bfly2s(pk& Xa, pk& Ya, pk& Xb, pk& Yb, const KC& k) {
    pk rXa = fma2(Yb, k.Tp, Xa);
    pk rYa = fma2(Xb, k.Tn, Ya);
    pk rXb = fma2(Ya, k.Tp, Xb);
    pk rYb = fma2(Xa, k.Tn, Yb);
    Xa = fma2(rXb, k.Tn, rXa);
    Ya = fma2(rYb, k.Tn, rYa);
    Xb = fma2(rXa, k.Tp, rXb);
    Yb = fma2(rYa, k.Tp, rYb);
}

// Gate on 4 register-index bits of a 16-pack array.
__device__ __forceinline__ void clean4(pk X[16], pk Y[16], const KC& k) {
#pragma unroll
    for (int bit = 0; bit < 4; bit++)
#pragma unroll
        for (int m = 0; m < 16; m++)
            if (!(m & (1 << bit))) {
                const int n = m | (1 << bit);
                bfly2s(X[m], Y[m], X[n], Y[n], k);
            }
}

// Gate on global bit 0 (the SIMD lane inside the pack): split RX/RY, scalar FFMA.
__device__ __forceinline__ void bflyL(pk& X, pk& Y, const KC& k) {
    const float t = TAU;
    float ax, bx, ay, by;
    unpack2(X, ax, bx); unpack2(Y, ay, by);
    const float rax = fmaf(t, by, ax), ray = fmaf(-t, bx, ay);
    const float rbx = fmaf(t, ay, bx), rby = fmaf(-t, ax, by);
    const float fax = fmaf(-t, rbx, rax), fay = fmaf(-t, rby, ray);
    const float fbx = fmaf(t, rax, rbx), fby = fmaf(t, ray, rby);
    X = pack2(fax, fbx); Y = pack2(fay, fby);
}

// CNOT-ring label permutation (wire w <-> bit 17-w). Linear over XOR.
__device__ __forceinline__ unsigned cmap(unsigned x) {
    unsigned sx = x;
    sx ^= sx >> 1; sx ^= sx >> 2; sx ^= sx >> 4; sx ^= sx >> 8; sx ^= sx >> 16;
    return (sx & 0x1FFFFu) | (((sx ^ (x >> 17)) & 1u) << 17);
}

#define PADC(c) ((c) + ((c) >> 4))

// ---------------------------------------------------------------------------
// LO pass: gates on x bits 0..12. Slab = 4096 cells (8192 amps). 256 thr x 16 packs.
// Phases: bit0 (SIMD) | cell bits 4..7 | 0..3 | 8..11 with 3 padded smem transposes.
// In-place (slab-local). first=1 reads fp32 input (x16).
// ---------------------------------------------------------------------------
__global__ void __launch_bounds__(256, 2) pass_lo(__half2* __restrict__ px,
                                                  __half2* __restrict__ py,
                                                  const float* __restrict__ re,
                                                  const float* __restrict__ im,
                                                  int first) {
    extern __shared__ pk sm[];
    pk* sx = sm;          // 4352
    pk* sy = sm + 4352;   // 4352
    const int t = threadIdx.x;
    const unsigned b = blockIdx.x >> 5, hi = blockIdx.x & 31;
    const size_t cb = ((size_t)b << 17) | ((size_t)hi << 12);
    const KC k = mkKC();

    pk X[16], Y[16];
    if (first) {
        const pk s16 = pack2(16.0f, 16.0f);
#pragma unroll
        for (int r = 0; r < 16; r++) {
            const size_t a = (cb + (unsigned)((r << 8) | t)) * 2;
            X[r] = mul2(*(const pk*)(re + a), s16);
            Y[r] = mul2(*(const pk*)(im + a), s16);
        }
    } else {
#pragma unroll
        for (int r = 0; r < 16; r++) {
            const size_t c = cb + (unsigned)((r << 8) | t);
            float2 fx = __half22float2(px[c]);
            float2 fy = __half22float2(py[c]);
            X[r] = pack2(fx.x, fx.y);
            Y[r] = pack2(fy.x, fy.y);
        }
    }

#pragma unroll
    for (int m = 0; m < 16; m++) bflyL(X[m], Y[m], k);   // x bit 0

    // layout0 (r<<8|t) -> layout1: reg = cell bits 4..7 (x bits 5..8)
#pragma unroll
    for (int r = 0; r < 16; r++) { const unsigned c = (r << 8) | t; sx[PADC(c)] = X[r]; sy[PADC(c)] = Y[r]; }
    __syncthreads();
#pragma unroll
    for (int r = 0; r < 16; r++) {
        const unsigned c = ((t >> 4) << 8) | (r << 4) | (t & 15);
        X[r] = sx[PADC(c)]; Y[r] = sy[PADC(c)];
    }
    clean4(X, Y, k);
    __syncthreads();

    // layout1 -> layout2: reg = cell bits 0..3 (x bits 1..4)
#pragma unroll
    for (int r = 0; r < 16; r++) {
        const unsigned c = ((t >> 4) << 8) | (r << 4) | (t & 15);
        sx[PADC(c)] = X[r]; sy[PADC(c)] = Y[r];
    }
    __syncthreads();
#pragma unroll
    for (int r = 0; r < 16; r++) {
        const unsigned c = (t << 4) | r;
        X[r] = sx[PADC(c)]; Y[r] = sy[PADC(c)];
    }
    clean4(X, Y, k);
    __syncthreads();

    // layout2 -> layout0: reg = cell bits 8..11 (x bits 9..12); store coalesced
#pragma unroll
    for (int r = 0; r < 16; r++) { const unsigned c = (t << 4) | r; sx[PADC(c)] = X[r]; sy[PADC(c)] = Y[r]; }
    __syncthreads();
#pragma unroll
    for (int r = 0; r < 16; r++) { const unsigned c = (r << 8) | t; X[r] = sx[PADC(c)]; Y[r] = sy[PADC(c)]; }
    clean4(X, Y, k);

#pragma unroll
    for (int r = 0; r < 16; r++) {
        const size_t c = cb + (unsigned)((r << 8) | t);
        float a0, a1;
        unpack2(X[r], a0, a1); px[c] = __floats2half2_rn(a0, a1);
        unpack2(Y[r], a0, a1); py[c] = __floats2half2_rn(a0, a1);
    }
}

// ---------------------------------------------------------------------------
// HI gates (x bits 13..17): cell bits 12..15 = reg r, cell bit 16 = lane bit 4.
// ---------------------------------------------------------------------------
__device__ __forceinline__ void hi_load_gates(const __half2* __restrict__ sx,
                                              const __half2* __restrict__ sy,
                                              size_t bb, unsigned clo, int L4,
                                              const KC& k, pk X[16], pk Y[16]) {
#pragma unroll
    for (int r = 0; r < 16; r++) {
        const size_t c = bb + (clo | ((unsigned)r << 12));
        float2 fx = __half22float2(sx[c]);
        float2 fy = __half22float2(sy[c]);
        X[r] = pack2(fx.x, fx.y);
        Y[r] = pack2(fy.x, fy.y);
    }
    clean4(X, Y, k);   // x bits 13..16

    // x bit 17 via shfl_xor(16), fused A-gate form; a-side (L4=0): e=-TAU, b-side: +TAU
    const float e = L4 ? TAU : -TAU;
    const pk eT = pack2(e, e), eT2 = pack2(e * TAU, e * TAU), eT2n = pack2(-e * TAU, -e * TAU);
#pragma unroll
    for (int r = 0; r < 16; r++) {
        pk pX = __shfl_xor_sync(0xffffffffu, X[r], 16);
        pk pY = __shfl_xor_sync(0xffffffffu, Y[r], 16);
        pk nX = fma2(pY, k.Tp, fma2(pX, eT, fma2(Y[r], eT2, X[r])));
        pk nY = fma2(pY, eT, fma2(pX, k.Tn, fma2(X[r], eT2n, Y[r])));
        X[r] = nX; Y[r] = nY;
    }
}

// ---------------------------------------------------------------------------
// HI pass + CNOT permutation folded into the store.
// dst cell pair (y, y^1): sources x and x^0x30001. Partner pack at
// (lane^16, reg^8); reassembled with prmt, parity-selected.
// ---------------------------------------------------------------------------
__global__ void __launch_bounds__(256) pass_hi(const __half2* __restrict__ sx,
                                               const __half2* __restrict__ sy,
                                               __half2* __restrict__ dx,
                                               __half2* __restrict__ dy) {
    const int t = threadIdx.x, L = t & 31, W = t >> 5, L4 = (L >> 4) & 1;
    const unsigned b = blockIdx.x >> 5, mid = blockIdx.x & 31;
    const size_t bb = (size_t)b << 17;
    const unsigned clo = (mid << 7) | ((unsigned)W << 4) | (unsigned)(L & 15)
                       | ((unsigned)L4 << 16);
    const KC k = mkKC();

    pk X[16], Y[16];
    hi_load_gates(sx, sy, bb, clo, L4, k, X, Y);

    unsigned hx[16], hy[16];
#pragma unroll
    for (int r = 0; r < 16; r++) {
        float a0, a1;
        unpack2(X[r], a0, a1); __half2 h = __floats2half2_rn(a0, a1); hx[r] = *(unsigned*)&h;
        unpack2(Y[r], a0, a1); h = __floats2half2_rn(a0, a1); hy[r] = *(unsigned*)&h;
    }

    const unsigned cB = cmap(clo << 1);
    const int pb = __popc(clo) & 1;
#pragma unroll
    for (int r = 0; r < 16; r++) {
        const unsigned phx = __shfl_xor_sync(0xffffffffu, hx[r ^ 8], 16);
        const unsigned phy = __shfl_xor_sync(0xffffffffu, hy[r ^ 8], 16);
        const int pr = pb ^ (__popc((unsigned)r) & 1);
        const unsigned ctrl = pr ? 0x5432u : 0x7610u;
        const unsigned ox = __byte_perm(hx[r], phx, ctrl);
        const unsigned oy = __byte_perm(hy[r], phy, ctrl);
        const unsigned y = cB ^ cmap((unsigned)r << 13) ^ (pr ? 0x20001u : 0u);
        const size_t dc = bb + (y >> 1);
        dx[dc] = *(const __half2*)&ox;
        dy[dc] = *(const __half2*)&oy;
    }
}

// ---------------------------------------------------------------------------
// Final: HI gates of layer 3 + weighted |.|^2 readout (perm + scales in dd).
// ---------------------------------------------------------------------------
__global__ void __launch_bounds__(256) pass_reduce(const __half2* __restrict__ sx,
                                                   const __half2* __restrict__ sy,
                                                   float* __restrict__ out) {
    const int t = threadIdx.x, L = t & 31, W = t >> 5, L4 = (L >> 4) & 1;
    const unsigned b = blockIdx.x >> 5, mid = blockIdx.x & 31;
    const size_t bb = (size_t)b << 17;
    const unsigned clo = (mid << 7) | ((unsigned)W << 4) | (unsigned)(L & 15)
                       | ((unsigned)L4 << 16);
    const KC k = mkKC();

    pk X[16], Y[16];
    hi_load_gates(sx, sy, bb, clo, L4, k, X, Y);

    pk acc = pack2(0.0f, 0.0f);
#pragma unroll
    for (int r = 0; r < 16; r++) {
        const unsigned c = clo | ((unsigned)r << 12);
        const pk dpk = *(const pk*)(g_dd + ((size_t)c << 1));
        pk p2 = fma2(Y[r], Y[r], mul2(X[r], X[r]));
        acc = fma2(p2, dpk, acc);
    }
    float a0, a1; unpack2(acc, a0, a1);
    float a = a0 + a1;
#pragma unroll
    for (int o = 16; o; o >>= 1) a += __shfl_xor_sync(0xffffffffu, a, o);
    __shared__ float ws[8];
    if (L == 0) ws[W] = a;
    __syncthreads();
    if (t < 8) {
        float s = ws[t];
#pragma unroll
        for (int o = 4; o; o >>= 1) s += __shfl_xor_sync(0xffu, s, o);
        if (t == 0) atomicAdd(out + b, s);
    }
}

// ---------------------------------------------------------------------------
// Init dd[] and out[b] = head_b (out is poisoned before each timed run).
// ---------------------------------------------------------------------------
__global__ void __launch_bounds__(256) init_kernel(const float* __restrict__ hw,
                                                   const float* __restrict__ hb,
                                                   float* __restrict__ out, float scale) {
    const unsigned x = blockIdx.x * 256u + threadIdx.x;
    if (x < DIM) {
        const unsigned y = cmap(x);
        float d = 0.0f;
#pragma unroll
        for (int w = 0; w < 18; w++)
            d += hw[w] * (((y >> (17 - w)) & 1u) ? -1.0f : 1.0f);
        g_dd[x] = d * scale;
    }
    if (x < BATCH) out[x] = hb[0];
}

extern "C" void kernel_launch(void* const* d_in, const int* in_sizes, int n_in,
                              void* d_out, int out_size) {
    (void)in_sizes; (void)n_in; (void)out_size;
    const float* re = (const float*)d_in[0];
    const float* im = (const float*)d_in[1];
    const float* hw = (const float*)d_in[2];
    const float* hb = (const float*)d_in[3];
    float* out = (float*)d_out;

    __half2 *x0, *y0, *x1, *y1;
    cudaGetSymbolAddress((void**)&x0, g_x0);
    cudaGetSymbolAddress((void**)&y0, g_y0);
    cudaGetSymbolAddress((void**)&x1, g_x1);
    cudaGetSymbolAddress((void**)&y1, g_y1);

    const int smemLO = 2 * 4352 * (int)sizeof(pk);  // 69632 B
    cudaFuncSetAttribute(pass_lo, cudaFuncAttributeMaxDynamicSharedMemorySize, smemLO);

    // deferred gate scale: amplitude c^108 -> prob (c^2)^108; /256 for x16 input
    const float scale = (float)(pow(0.9975020826390129, 108.0) / 256.0);

    const int grid = BATCH * 32;  // 2048

    init_kernel<<<DIM / 256, 256>>>(hw, hb, out, scale);

    // Layer 1
    pass_lo<<<grid, 256, smemLO>>>(x0, y0, re, im, 1);
    pass_hi<<<grid, 256>>>(x0, y0, x1, y1);
    // Layer 2
    pass_lo<<<grid, 256, smemLO>>>(x1, y1, re, im, 0);
    pass_hi<<<grid, 256>>>(x1, y1, x0, y0);
    // Layer 3
    pass_lo<<<grid, 256, smemLO>>>(x0, y0, re, im, 0);
    pass_reduce<<<grid, 256>>>(x0, y0, out);
}